// round 1
// baseline (speedup 1.0000x reference)
#include <cuda_runtime.h>
#include <cuda_bf16.h>
#include <math.h>

// ---------------------------------------------------------------------------
// Problem constants
// ---------------------------------------------------------------------------
#define T_TOK   1024
#define HID     2880
#define NH      64
#define KVH     8
#define HD      64
#define INTER   2880
#define QKV_DIM (HD*(NH+2*KVH))      // 5120
#define O_DIM   (NH*HD)              // 4096
#define U_DIM   (2*INTER)            // 5760
#define SM_SCALE 0.125f              // 1/sqrt(64)
#define EPSF    1e-5f

// ---------------------------------------------------------------------------
// Scratch (allocation-free: __device__ globals)
// ---------------------------------------------------------------------------
__device__ float g_t  [T_TOK * HID];     // normed activations
__device__ float g_qkv[T_TOK * QKV_DIM];
__device__ float g_o  [T_TOK * O_DIM];
__device__ float g_h  [T_TOK * HID];
__device__ float g_u  [T_TOK * U_DIM];
__device__ float g_act[T_TOK * INTER];

// ---------------------------------------------------------------------------
// RMSNorm: one block per row
// ---------------------------------------------------------------------------
__global__ __launch_bounds__(256) void rmsnorm_kernel(
    const float* __restrict__ x, const float* __restrict__ scale,
    float* __restrict__ out)
{
    const int row = blockIdx.x;
    const float* xr = x + (size_t)row * HID;
    float s = 0.f;
    for (int i = threadIdx.x; i < HID; i += 256) { float v = xr[i]; s += v * v; }
    __shared__ float red[256];
    red[threadIdx.x] = s;
    __syncthreads();
    for (int off = 128; off > 0; off >>= 1) {
        if (threadIdx.x < off) red[threadIdx.x] += red[threadIdx.x + off];
        __syncthreads();
    }
    const float inv = rsqrtf(red[0] / (float)HID + EPSF);
    float* orow = out + (size_t)row * HID;
    for (int i = threadIdx.x; i < HID; i += 256)
        orow[i] = xr[i] * inv * scale[i];
}

// ---------------------------------------------------------------------------
// SGEMM: C[M,N] = A[M,K] @ W[N,K]^T + bias[N] (+ res[M,N])
// BM=128, BN=64, BK=8, 256 threads, 8x4 micro-tile.
// ---------------------------------------------------------------------------
#define BM 128
#define BN 64
#define BK 8

template<bool RES>
__global__ __launch_bounds__(256) void sgemm_kernel(
    const float* __restrict__ A, const float* __restrict__ W,
    const float* __restrict__ bias, const float* __restrict__ res,
    float* __restrict__ C, int M, int N, int K)
{
    __shared__ float As[BK][BM];
    __shared__ float Bs[BK][BN];

    const int tid = threadIdx.x;
    const int bx = blockIdx.x;   // N tiles
    const int by = blockIdx.y;   // M tiles
    const int tx = tid & 15;     // 16 cols of threads (4 outs each)
    const int ty = tid >> 4;     // 16 rows of threads (8 outs each)

    // A tile loader: 128 rows x 8 k; 256 thr -> one float4 each
    const int arow = tid >> 1;
    const int acol = (tid & 1) * 4;
    const float* Aptr = A + (size_t)(by * BM + arow) * K + acol;

    // W tile loader: 64 rows x 8 k; 256 thr -> one float2 each
    const int brow = tid >> 2;
    const int bcol = (tid & 3) * 2;
    const float* Wptr = W + (size_t)(bx * BN + brow) * K + bcol;

    float acc[8][4];
    #pragma unroll
    for (int i = 0; i < 8; i++)
        #pragma unroll
        for (int j = 0; j < 4; j++) acc[i][j] = 0.f;

    for (int kt = 0; kt < K; kt += BK) {
        float4 av = *(const float4*)(Aptr + kt);
        As[acol + 0][arow] = av.x;
        As[acol + 1][arow] = av.y;
        As[acol + 2][arow] = av.z;
        As[acol + 3][arow] = av.w;
        float2 bv = *(const float2*)(Wptr + kt);
        Bs[bcol + 0][brow] = bv.x;
        Bs[bcol + 1][brow] = bv.y;
        __syncthreads();

        #pragma unroll
        for (int kk = 0; kk < BK; kk++) {
            float a[8], b[4];
            #pragma unroll
            for (int i = 0; i < 8; i++) a[i] = As[kk][ty * 8 + i];
            #pragma unroll
            for (int j = 0; j < 4; j++) b[j] = Bs[kk][tx * 4 + j];
            #pragma unroll
            for (int i = 0; i < 8; i++)
                #pragma unroll
                for (int j = 0; j < 4; j++)
                    acc[i][j] += a[i] * b[j];
        }
        __syncthreads();
    }

    const int n0 = bx * BN + tx * 4;
    float4 bv = *(const float4*)(bias + n0);
    #pragma unroll
    for (int i = 0; i < 8; i++) {
        const int m = by * BM + ty * 8 + i;
        float4 v;
        v.x = acc[i][0] + bv.x;
        v.y = acc[i][1] + bv.y;
        v.z = acc[i][2] + bv.z;
        v.w = acc[i][3] + bv.w;
        if (RES) {
            float4 rv = *(const float4*)(res + (size_t)m * N + n0);
            v.x += rv.x; v.y += rv.y; v.z += rv.z; v.w += rv.w;
        }
        *(float4*)(C + (size_t)m * N + n0) = v;
    }
}

// ---------------------------------------------------------------------------
// RoPE (YaRN-style scaled freqs, matching the reference formula).
// grid (T, NH+KVH), 32 threads. Applied in-place on g_qkv.
// ---------------------------------------------------------------------------
__global__ void rope_kernel(float* __restrict__ qkv)
{
    const int t = blockIdx.x;
    const int head = blockIdx.y;            // 0..63 = q heads, 64..71 = k heads
    const int i = threadIdx.x;              // 0..31 (half-dim index)

    float* base;
    if (head < NH) base = qkv + (size_t)t * QKV_DIM + head * HD;
    else           base = qkv + (size_t)t * QKV_DIM + NH * HD + (head - NH) * HD;

    const float PI = 3.14159265358979323846f;
    const float rope_base = 150000.f;
    const float freq = powf(rope_base, (float)i / 32.f);
    const float conc = 0.1f * logf(32.f) + 1.f;
    const float lg = logf(rope_base);
    const float low  = 32.f * logf(4096.f / (32.f * 2.f * PI)) / lg;
    const float high = 32.f * logf(4096.f / (2.f * PI)) / lg;
    const float interp = 1.f / (32.f * freq);
    const float extrap = 1.f / freq;
    float ramp = ((float)i - low) / (high - low);
    ramp = fminf(fmaxf(ramp, 0.f), 1.f);
    const float mask = 1.f - ramp;
    const float invf = interp * (1.f - mask) + extrap * mask;
    const float ang = (float)t * invf;
    const float c = cosf(ang) * conc;
    const float s = sinf(ang) * conc;

    const float x1 = base[i];
    const float x2 = base[i + 32];
    base[i]      = x1 * c - x2 * s;
    base[i + 32] = x2 * c + x1 * s;
}

// ---------------------------------------------------------------------------
// Causal GQA flash attention, fp32.
// grid (16 q-tiles, 64 heads), 256 threads, 64x64 tiles, dynamic smem.
// ---------------------------------------------------------------------------
#define QT 64
#define ATTN_SMEM ((4 * 64 * 65 + 3 * 64) * (int)sizeof(float))

__global__ __launch_bounds__(256) void attn_kernel(
    const float* __restrict__ qkv, float* __restrict__ o)
{
    extern __shared__ float sm[];
    float* Qs   = sm;                 // 64 x 65
    float* Ks   = Qs + 64 * 65;
    float* Vs   = Ks + 64 * 65;
    float* Ss   = Vs + 64 * 65;
    float* mrow = Ss + 64 * 65;
    float* lrow = mrow + 64;
    float* arow = lrow + 64;

    const int qt = blockIdx.x;
    const int h  = blockIdx.y;
    const int kh = h >> 3;
    const int tid = threadIdx.x;
    const int ty = tid >> 4, tx = tid & 15;

    for (int i = tid; i < 64 * 64; i += 256) {
        int r = i >> 6, d = i & 63;
        Qs[r * 65 + d] = qkv[(size_t)(qt * QT + r) * QKV_DIM + h * HD + d];
    }
    if (tid < 64) { mrow[tid] = -1e30f; lrow[tid] = 0.f; }
    float oacc[4][4];
    #pragma unroll
    for (int i = 0; i < 4; i++)
        #pragma unroll
        for (int j = 0; j < 4; j++) oacc[i][j] = 0.f;
    __syncthreads();

    for (int kt = 0; kt <= qt; kt++) {
        for (int i = tid; i < 64 * 64; i += 256) {
            int r = i >> 6, d = i & 63;
            size_t base = (size_t)(kt * QT + r) * QKV_DIM;
            Ks[r * 65 + d] = qkv[base + NH * HD + kh * HD + d];
            Vs[r * 65 + d] = qkv[base + (NH + KVH) * HD + kh * HD + d];
        }
        __syncthreads();

        // S = Q K^T * scale
        float acc[4][4];
        #pragma unroll
        for (int i = 0; i < 4; i++)
            #pragma unroll
            for (int j = 0; j < 4; j++) acc[i][j] = 0.f;
        #pragma unroll 8
        for (int d = 0; d < 64; d++) {
            float a[4], b[4];
            #pragma unroll
            for (int i = 0; i < 4; i++) a[i] = Qs[(ty * 4 + i) * 65 + d];
            #pragma unroll
            for (int j = 0; j < 4; j++) b[j] = Ks[(tx * 4 + j) * 65 + d];
            #pragma unroll
            for (int i = 0; i < 4; i++)
                #pragma unroll
                for (int j = 0; j < 4; j++)
                    acc[i][j] += a[i] * b[j];
        }
        #pragma unroll
        for (int i = 0; i < 4; i++)
            #pragma unroll
            for (int j = 0; j < 4; j++)
                Ss[(ty * 4 + i) * 65 + tx * 4 + j] = acc[i][j] * SM_SCALE;
        __syncthreads();

        // online softmax row pass (64 threads own one row each)
        if (tid < 64) {
            const int r = tid;
            const int cmax = (kt == qt) ? (r + 1) : 64;
            const float mold = mrow[r];
            float mx = mold;
            for (int c = 0; c < cmax; c++) mx = fmaxf(mx, Ss[r * 65 + c]);
            const float alpha = expf(mold - mx);
            float sum = 0.f;
            for (int c = 0; c < 64; c++) {
                float p = (c < cmax) ? expf(Ss[r * 65 + c] - mx) : 0.f;
                Ss[r * 65 + c] = p;
                sum += p;
            }
            mrow[r] = mx;
            lrow[r] = lrow[r] * alpha + sum;
            arow[r] = alpha;
        }
        __syncthreads();

        // O = O*alpha + P @ V
        float pv[4][4];
        #pragma unroll
        for (int i = 0; i < 4; i++)
            #pragma unroll
            for (int j = 0; j < 4; j++) pv[i][j] = 0.f;
        #pragma unroll 8
        for (int c = 0; c < 64; c++) {
            float p[4], v[4];
            #pragma unroll
            for (int i = 0; i < 4; i++) p[i] = Ss[(ty * 4 + i) * 65 + c];
            #pragma unroll
            for (int j = 0; j < 4; j++) v[j] = Vs[c * 65 + tx * 4 + j];
            #pragma unroll
            for (int i = 0; i < 4; i++)
                #pragma unroll
                for (int j = 0; j < 4; j++)
                    pv[i][j] += p[i] * v[j];
        }
        float al[4];
        #pragma unroll
        for (int i = 0; i < 4; i++) al[i] = arow[ty * 4 + i];
        #pragma unroll
        for (int i = 0; i < 4; i++)
            #pragma unroll
            for (int j = 0; j < 4; j++)
                oacc[i][j] = oacc[i][j] * al[i] + pv[i][j];
        __syncthreads();
    }

    #pragma unroll
    for (int i = 0; i < 4; i++) {
        const float linv = 1.f / lrow[ty * 4 + i];
        const int m = qt * QT + ty * 4 + i;
        #pragma unroll
        for (int j = 0; j < 4; j++)
            o[(size_t)m * O_DIM + h * HD + tx * 4 + j] = oacc[i][j] * linv;
    }
}

// ---------------------------------------------------------------------------
// Clamped SwiGLU: act[t][c] from u[t][2c], u[t][2c+1]
// ---------------------------------------------------------------------------
__global__ __launch_bounds__(256) void act_kernel(
    const float* __restrict__ u, float* __restrict__ act)
{
    const int idx = blockIdx.x * 256 + threadIdx.x;
    if (idx >= T_TOK * INTER) return;
    const int row = idx / INTER, col = idx - row * INTER;
    float g   = u[(size_t)row * U_DIM + 2 * col];
    float lin = u[(size_t)row * U_DIM + 2 * col + 1];
    g   = fminf(g, 7.f);
    lin = fminf(fmaxf(lin, -7.f), 7.f);
    const float sg = 1.f / (1.f + expf(-1.702f * g));
    act[idx] = g * sg * (lin + 1.f);
}

// ---------------------------------------------------------------------------
// Launch
// ---------------------------------------------------------------------------
extern "C" void kernel_launch(void* const* d_in, const int* in_sizes, int n_in,
                              void* d_out, int out_size)
{
    const float* x        = (const float*)d_in[0];
    const float* an_scale = (const float*)d_in[1];
    const float* wqkv     = (const float*)d_in[2];
    const float* bqkv     = (const float*)d_in[3];
    const float* wout     = (const float*)d_in[4];
    const float* bout     = (const float*)d_in[5];
    const float* mn_scale = (const float*)d_in[6];
    const float* w1       = (const float*)d_in[7];
    const float* b1       = (const float*)d_in[8];
    const float* w2       = (const float*)d_in[9];
    const float* b2       = (const float*)d_in[10];
    float* out = (float*)d_out;

    static float *t_p = nullptr, *qkv_p, *o_p, *h_p, *u_p, *act_p;
    if (!t_p) {
        cudaGetSymbolAddress((void**)&t_p,   g_t);
        cudaGetSymbolAddress((void**)&qkv_p, g_qkv);
        cudaGetSymbolAddress((void**)&o_p,   g_o);
        cudaGetSymbolAddress((void**)&h_p,   g_h);
        cudaGetSymbolAddress((void**)&u_p,   g_u);
        cudaGetSymbolAddress((void**)&act_p, g_act);
    }
    // capture-safe, idempotent
    cudaFuncSetAttribute(attn_kernel,
                         cudaFuncAttributeMaxDynamicSharedMemorySize, ATTN_SMEM);

    // 1) attn rmsnorm
    rmsnorm_kernel<<<T_TOK, 256>>>(x, an_scale, t_p);

    // 2) QKV GEMM: [1024,2880] x [5120,2880]^T
    {
        dim3 grid(QKV_DIM / BN, T_TOK / BM);
        sgemm_kernel<false><<<grid, 256>>>(t_p, wqkv, bqkv, nullptr, qkv_p,
                                           T_TOK, QKV_DIM, HID);
    }

    // 3) RoPE on q + k heads
    {
        dim3 grid(T_TOK, NH + KVH);
        rope_kernel<<<grid, 32>>>(qkv_p);
    }

    // 4) attention
    {
        dim3 grid(T_TOK / QT, NH);
        attn_kernel<<<grid, 256, ATTN_SMEM>>>(qkv_p, o_p);
    }

    // 5) out GEMM + residual: h = x + o @ wout^T + bout
    {
        dim3 grid(HID / BN, T_TOK / BM);
        sgemm_kernel<true><<<grid, 256>>>(o_p, wout, bout, x, h_p,
                                          T_TOK, HID, O_DIM);
    }

    // 6) mlp rmsnorm
    rmsnorm_kernel<<<T_TOK, 256>>>(h_p, mn_scale, t_p);

    // 7) MLP up GEMM
    {
        dim3 grid(U_DIM / BN, T_TOK / BM);
        sgemm_kernel<false><<<grid, 256>>>(t_p, w1, b1, nullptr, u_p,
                                           T_TOK, U_DIM, HID);
    }

    // 8) activation
    act_kernel<<<(T_TOK * INTER + 255) / 256, 256>>>(u_p, act_p);

    // 9) MLP down GEMM + residual -> out
    {
        dim3 grid(HID / BN, T_TOK / BM);
        sgemm_kernel<true><<<grid, 256>>>(act_p, w2, b2, h_p, out,
                                          T_TOK, HID, INTER);
    }
}

// round 3
// speedup vs baseline: 1.2315x; 1.2315x over previous
#include <cuda_runtime.h>
#include <cuda_bf16.h>
#include <math.h>
#include <stdint.h>

// ---------------------------------------------------------------------------
// Problem constants
// ---------------------------------------------------------------------------
#define T_TOK   1024
#define HID     2880
#define NH      64
#define KVH     8
#define HD      64
#define INTER   2880
#define QKV_DIM (HD*(NH+2*KVH))      // 5120
#define O_DIM   (NH*HD)              // 4096
#define U_DIM   (2*INTER)            // 5760
#define SM_SCALE 0.125f
#define EPSF    1e-5f

#define NPAD_2880 2944               // 23*128

// ---------------------------------------------------------------------------
// Scratch (__device__ globals; allocation-free)
// ---------------------------------------------------------------------------
__device__ float g_t  [T_TOK * HID];
__device__ float g_qkv[T_TOK * QKV_DIM];
__device__ float g_o  [T_TOK * O_DIM];
__device__ float g_h  [T_TOK * HID];
__device__ float g_u  [T_TOK * U_DIM];
__device__ float g_act[T_TOK * INTER];

// split-bf16 buffers: row layout [hi(0..K-1) | lo(K..2K-1)], row stride 2K
__device__ __align__(256) __nv_bfloat16 g_w2_qkv[QKV_DIM * 2 * HID];
__device__ __align__(256) __nv_bfloat16 g_w2_out[NPAD_2880 * 2 * O_DIM];
__device__ __align__(256) __nv_bfloat16 g_w2_up [U_DIM   * 2 * HID];
__device__ __align__(256) __nv_bfloat16 g_w2_dn [NPAD_2880 * 2 * INTER];
__device__ __align__(256) __nv_bfloat16 g_a2    [T_TOK * 2 * O_DIM];

// ---------------------------------------------------------------------------
// PTX helpers (base-target-safe: cp.async / ldmatrix / mma.sync only)
// ---------------------------------------------------------------------------
__device__ __forceinline__ uint32_t smem_u32(const void* p) {
    uint32_t a;
    asm("{ .reg .u64 t; cvta.to.shared.u64 t, %1; cvt.u32.u64 %0, t; }" : "=r"(a) : "l"(p));
    return a;
}
__device__ __forceinline__ void cp16(uint32_t dst, const void* src) {
    asm volatile("cp.async.cg.shared.global [%0], [%1], 16;" :: "r"(dst), "l"(src));
}
__device__ __forceinline__ void cp_commit() {
    asm volatile("cp.async.commit_group;" ::: "memory");
}
__device__ __forceinline__ void cp_wait1() {
    asm volatile("cp.async.wait_group 1;" ::: "memory");
}
__device__ __forceinline__ void cp_wait0() {
    asm volatile("cp.async.wait_group 0;" ::: "memory");
}
__device__ __forceinline__ void ldmatrix_x4(uint32_t& r0, uint32_t& r1,
                                            uint32_t& r2, uint32_t& r3, uint32_t addr) {
    asm volatile("ldmatrix.sync.aligned.m8n8.x4.shared.b16 {%0,%1,%2,%3}, [%4];"
        : "=r"(r0), "=r"(r1), "=r"(r2), "=r"(r3) : "r"(addr));
}
__device__ __forceinline__ void mma_bf16(float& c0, float& c1, float& c2, float& c3,
                                         uint32_t a0, uint32_t a1, uint32_t a2, uint32_t a3,
                                         uint32_t b0, uint32_t b1) {
    asm volatile("mma.sync.aligned.m16n8k16.row.col.f32.bf16.bf16.f32 "
        "{%0,%1,%2,%3}, {%4,%5,%6,%7}, {%8,%9}, {%0,%1,%2,%3};"
        : "+f"(c0), "+f"(c1), "+f"(c2), "+f"(c3)
        : "r"(a0), "r"(a1), "r"(a2), "r"(a3), "r"(b0), "r"(b1));
}

// ---------------------------------------------------------------------------
// fp32 -> [hi | lo] bf16 split conversion. Row stride 2K; rows >= Nrows zeroed.
// ---------------------------------------------------------------------------
__global__ __launch_bounds__(256) void convert_split_kernel(
    const float* __restrict__ X, __nv_bfloat16* __restrict__ X2,
    int Nrows, int K, int Npad)
{
    const long long idx = (long long)blockIdx.x * 256 + threadIdx.x;
    const int kq = K >> 2;
    const long long total = (long long)Npad * kq;
    if (idx >= total) return;
    const int n = (int)(idx / kq);
    const int k = (int)(idx - (long long)n * kq) * 4;
    float4 v = make_float4(0.f, 0.f, 0.f, 0.f);
    if (n < Nrows) v = *(const float4*)(X + (size_t)n * K + k);
    __nv_bfloat16 hx = __float2bfloat16(v.x);
    __nv_bfloat16 hy = __float2bfloat16(v.y);
    __nv_bfloat16 hz = __float2bfloat16(v.z);
    __nv_bfloat16 hw = __float2bfloat16(v.w);
    float lx = v.x - __bfloat162float(hx);
    float ly = v.y - __bfloat162float(hy);
    float lz = v.z - __bfloat162float(hz);
    float lw = v.w - __bfloat162float(hw);
    __nv_bfloat16* row = X2 + (size_t)n * 2 * K;
    __nv_bfloat162* ph = (__nv_bfloat162*)(row + k);
    ph[0] = __halves2bfloat162(hx, hy);
    ph[1] = __halves2bfloat162(hz, hw);
    __nv_bfloat162* pl = (__nv_bfloat162*)(row + K + k);
    pl[0] = __floats2bfloat162_rn(lx, ly);
    pl[1] = __floats2bfloat162_rn(lz, lw);
}

// ---------------------------------------------------------------------------
// Split-bf16 GEMM via mma.sync: C[m,n] = sum_k A[m,k]*W[n,k] (+bias +res)
// 128x128 CTA tile, BK=64 bf16, double-buffered cp.async.
// 8 warps as 2(m) x 4(n); warp tile 64x32; m16n8k16 bf16 HMMA.
// smem row stride 144B (64 bf16 data + 8 pad) -> conflict-free ldmatrix.
// ---------------------------------------------------------------------------
#define KSTRIDE_B 144                 // bytes per smem row
#define TILE_B   (128 * KSTRIDE_B)    // 18432 bytes per tile
#define GSMEM_TOTAL (4 * TILE_B)      // 73728

__device__ __forceinline__ void fill_tiles_mma(
    uint32_t aT, uint32_t bT,
    const __nv_bfloat16* __restrict__ A2, const __nv_bfloat16* __restrict__ W2,
    int Kp, int m0, int n0, int ka, int kw, int tid)
{
    #pragma unroll
    for (int i = 0; i < 4; i++) {
        int q = tid + 256 * i;
        int r = q >> 3, c = q & 7;
        cp16(aT + r * KSTRIDE_B + c * 16, A2 + (size_t)(m0 + r) * Kp + ka + c * 8);
    }
    #pragma unroll
    for (int i = 0; i < 4; i++) {
        int q = tid + 256 * i;
        int r = q >> 3, c = q & 7;
        cp16(bT + r * KSTRIDE_B + c * 16, W2 + (size_t)(n0 + r) * Kp + kw + c * 8);
    }
}

template<bool RES>
__global__ __launch_bounds__(256) void mma_gemm(
    const __nv_bfloat16* __restrict__ A2, const __nv_bfloat16* __restrict__ W2,
    const float* __restrict__ bias, const float* __restrict__ res,
    float* __restrict__ C, int K, int Nout)
{
    extern __shared__ char smem[];
    const uint32_t sbase = smem_u32(smem);
    const uint32_t tA[2] = { sbase,              sbase + 2 * TILE_B };
    const uint32_t tB[2] = { sbase + TILE_B,     sbase + 3 * TILE_B };

    const int tid  = threadIdx.x;
    const int wid  = tid >> 5;
    const int lane = tid & 31;
    const int wm   = wid >> 2;        // 0..1  (64 rows each)
    const int wn   = wid & 3;         // 0..3  (32 cols each)
    const int m0 = blockIdx.x * 128;
    const int n0 = blockIdx.y * 128;
    const int Kp = 2 * K;
    const int NCseg = K >> 6;
    const int NC = 3 * NCseg;

    // ldmatrix base addresses (within a tile)
    // A frag (m16k16): lanes 0-15 -> rows 0-15 @k0, lanes 16-31 -> rows 0-15 @k8
    const uint32_t aOff = (uint32_t)((wm * 64 + (lane & 15)) * KSTRIDE_B + (lane >> 4) * 16);
    // B frag pair (n16k16): n = (lane&7) + ((lane>>4)&1)*8, k = ((lane>>3)&1)*8
    const uint32_t bOff = (uint32_t)((wn * 32 + (lane & 7) + ((lane >> 4) & 1) * 8) * KSTRIDE_B
                                     + ((lane >> 3) & 1) * 16);

    float acc[4][4][4];
    #pragma unroll
    for (int i = 0; i < 4; i++)
        #pragma unroll
        for (int j = 0; j < 4; j++)
            #pragma unroll
            for (int q = 0; q < 4; q++) acc[i][j][q] = 0.f;

    fill_tiles_mma(tA[0], tB[0], A2, W2, Kp, m0, n0, 0, 0, tid);
    cp_commit();

    for (int c = 0; c < NC; c++) {
        const int b = c & 1;
        if (c + 1 < NC) {
            const int nb = (c + 1) & 1;
            const int cn = c + 1;
            const int seg = cn / NCseg;
            const int kk = (cn - seg * NCseg) << 6;
            const int ka = (seg < 2) ? kk : K + kk;
            const int kw = (seg == 1) ? K + kk : kk;
            fill_tiles_mma(tA[nb], tB[nb], A2, W2, Kp, m0, n0, ka, kw, tid);
            cp_commit();
            cp_wait1();
        } else {
            cp_wait0();
        }
        __syncthreads();

        #pragma unroll
        for (int ks = 0; ks < 4; ks++) {
            const uint32_t kb = (uint32_t)(ks * 32);    // 16 bf16 = 32 bytes
            uint32_t a[4][4];
            #pragma unroll
            for (int mf = 0; mf < 4; mf++)
                ldmatrix_x4(a[mf][0], a[mf][1], a[mf][2], a[mf][3],
                            tA[b] + aOff + mf * 16 * KSTRIDE_B + kb);
            uint32_t bb[4][2];
            #pragma unroll
            for (int bf = 0; bf < 2; bf++) {
                uint32_t r0, r1, r2, r3;
                ldmatrix_x4(r0, r1, r2, r3,
                            tB[b] + bOff + bf * 16 * KSTRIDE_B + kb);
                bb[bf * 2 + 0][0] = r0; bb[bf * 2 + 0][1] = r1;
                bb[bf * 2 + 1][0] = r2; bb[bf * 2 + 1][1] = r3;
            }
            #pragma unroll
            for (int mf = 0; mf < 4; mf++)
                #pragma unroll
                for (int nf = 0; nf < 4; nf++)
                    mma_bf16(acc[mf][nf][0], acc[mf][nf][1],
                             acc[mf][nf][2], acc[mf][nf][3],
                             a[mf][0], a[mf][1], a[mf][2], a[mf][3],
                             bb[nf][0], bb[nf][1]);
        }
        __syncthreads();
    }

    // Epilogue: lane holds (row g, cols 2t..2t+1) and (row g+8) per frag
    const int g = lane >> 2;
    const int t = lane & 3;
    #pragma unroll
    for (int nf = 0; nf < 4; nf++) {
        const int col = n0 + wn * 32 + nf * 8 + t * 2;
        if (col >= Nout) continue;
        const float bx = bias[col], by = bias[col + 1];
        #pragma unroll
        for (int mf = 0; mf < 4; mf++) {
            const int r0 = m0 + wm * 64 + mf * 16 + g;
            float2 v0 = make_float2(acc[mf][nf][0] + bx, acc[mf][nf][1] + by);
            float2 v1 = make_float2(acc[mf][nf][2] + bx, acc[mf][nf][3] + by);
            if (RES) {
                const float2 q0 = *(const float2*)(res + (size_t)r0 * Nout + col);
                const float2 q1 = *(const float2*)(res + (size_t)(r0 + 8) * Nout + col);
                v0.x += q0.x; v0.y += q0.y; v1.x += q1.x; v1.y += q1.y;
            }
            *(float2*)(C + (size_t)r0 * Nout + col) = v0;
            *(float2*)(C + (size_t)(r0 + 8) * Nout + col) = v1;
        }
    }
}

// ---------------------------------------------------------------------------
// RMSNorm
// ---------------------------------------------------------------------------
__global__ __launch_bounds__(256) void rmsnorm_kernel(
    const float* __restrict__ x, const float* __restrict__ scale,
    float* __restrict__ out)
{
    const int row = blockIdx.x;
    const float* xr = x + (size_t)row * HID;
    float s = 0.f;
    for (int i = threadIdx.x; i < HID; i += 256) { float v = xr[i]; s += v * v; }
    __shared__ float red[256];
    red[threadIdx.x] = s;
    __syncthreads();
    for (int off = 128; off > 0; off >>= 1) {
        if (threadIdx.x < off) red[threadIdx.x] += red[threadIdx.x + off];
        __syncthreads();
    }
    const float inv = rsqrtf(red[0] / (float)HID + EPSF);
    float* orow = out + (size_t)row * HID;
    for (int i = threadIdx.x; i < HID; i += 256)
        orow[i] = xr[i] * inv * scale[i];
}

// ---------------------------------------------------------------------------
// RoPE
// ---------------------------------------------------------------------------
__global__ void rope_kernel(float* __restrict__ qkv)
{
    const int t = blockIdx.x;
    const int head = blockIdx.y;
    const int i = threadIdx.x;

    float* base;
    if (head < NH) base = qkv + (size_t)t * QKV_DIM + head * HD;
    else           base = qkv + (size_t)t * QKV_DIM + NH * HD + (head - NH) * HD;

    const float PI = 3.14159265358979323846f;
    const float rope_base = 150000.f;
    const float freq = powf(rope_base, (float)i / 32.f);
    const float conc = 0.1f * logf(32.f) + 1.f;
    const float lg = logf(rope_base);
    const float low  = 32.f * logf(4096.f / (32.f * 2.f * PI)) / lg;
    const float high = 32.f * logf(4096.f / (2.f * PI)) / lg;
    const float interp = 1.f / (32.f * freq);
    const float extrap = 1.f / freq;
    float ramp = ((float)i - low) / (high - low);
    ramp = fminf(fmaxf(ramp, 0.f), 1.f);
    const float mask = 1.f - ramp;
    const float invf = interp * (1.f - mask) + extrap * mask;
    const float ang = (float)t * invf;
    const float c = cosf(ang) * conc;
    const float s = sinf(ang) * conc;

    const float x1 = base[i];
    const float x2 = base[i + 32];
    base[i]      = x1 * c - x2 * s;
    base[i + 32] = x2 * c + x1 * s;
}

// ---------------------------------------------------------------------------
// Causal GQA flash attention (fp32)
// ---------------------------------------------------------------------------
#define QT 64
#define ATTN_SMEM ((4 * 64 * 65 + 3 * 64) * (int)sizeof(float))

__global__ __launch_bounds__(256) void attn_kernel(
    const float* __restrict__ qkv, float* __restrict__ o)
{
    extern __shared__ float sm[];
    float* Qs   = sm;
    float* Ks   = Qs + 64 * 65;
    float* Vs   = Ks + 64 * 65;
    float* Ss   = Vs + 64 * 65;
    float* mrow = Ss + 64 * 65;
    float* lrow = mrow + 64;
    float* arow = lrow + 64;

    const int qt = blockIdx.x;
    const int h  = blockIdx.y;
    const int kh = h >> 3;
    const int tid = threadIdx.x;
    const int ty = tid >> 4, tx = tid & 15;

    for (int i = tid; i < 64 * 64; i += 256) {
        int r = i >> 6, d = i & 63;
        Qs[r * 65 + d] = qkv[(size_t)(qt * QT + r) * QKV_DIM + h * HD + d];
    }
    if (tid < 64) { mrow[tid] = -1e30f; lrow[tid] = 0.f; }
    float oacc[4][4];
    #pragma unroll
    for (int i = 0; i < 4; i++)
        #pragma unroll
        for (int j = 0; j < 4; j++) oacc[i][j] = 0.f;
    __syncthreads();

    for (int kt = 0; kt <= qt; kt++) {
        for (int i = tid; i < 64 * 64; i += 256) {
            int r = i >> 6, d = i & 63;
            size_t base = (size_t)(kt * QT + r) * QKV_DIM;
            Ks[r * 65 + d] = qkv[base + NH * HD + kh * HD + d];
            Vs[r * 65 + d] = qkv[base + (NH + KVH) * HD + kh * HD + d];
        }
        __syncthreads();

        float acc[4][4];
        #pragma unroll
        for (int i = 0; i < 4; i++)
            #pragma unroll
            for (int j = 0; j < 4; j++) acc[i][j] = 0.f;
        #pragma unroll 8
        for (int d = 0; d < 64; d++) {
            float a[4], b[4];
            #pragma unroll
            for (int i = 0; i < 4; i++) a[i] = Qs[(ty * 4 + i) * 65 + d];
            #pragma unroll
            for (int j = 0; j < 4; j++) b[j] = Ks[(tx * 4 + j) * 65 + d];
            #pragma unroll
            for (int i = 0; i < 4; i++)
                #pragma unroll
                for (int j = 0; j < 4; j++)
                    acc[i][j] += a[i] * b[j];
        }
        #pragma unroll
        for (int i = 0; i < 4; i++)
            #pragma unroll
            for (int j = 0; j < 4; j++)
                Ss[(ty * 4 + i) * 65 + tx * 4 + j] = acc[i][j] * SM_SCALE;
        __syncthreads();

        if (tid < 64) {
            const int r = tid;
            const int cmax = (kt == qt) ? (r + 1) : 64;
            const float mold = mrow[r];
            float mx = mold;
            for (int c = 0; c < cmax; c++) mx = fmaxf(mx, Ss[r * 65 + c]);
            const float alpha = expf(mold - mx);
            float sum = 0.f;
            for (int c = 0; c < 64; c++) {
                float p = (c < cmax) ? expf(Ss[r * 65 + c] - mx) : 0.f;
                Ss[r * 65 + c] = p;
                sum += p;
            }
            mrow[r] = mx;
            lrow[r] = lrow[r] * alpha + sum;
            arow[r] = alpha;
        }
        __syncthreads();

        float pv[4][4];
        #pragma unroll
        for (int i = 0; i < 4; i++)
            #pragma unroll
            for (int j = 0; j < 4; j++) pv[i][j] = 0.f;
        #pragma unroll 8
        for (int c = 0; c < 64; c++) {
            float p[4], v[4];
            #pragma unroll
            for (int i = 0; i < 4; i++) p[i] = Ss[(ty * 4 + i) * 65 + c];
            #pragma unroll
            for (int j = 0; j < 4; j++) v[j] = Vs[c * 65 + tx * 4 + j];
            #pragma unroll
            for (int i = 0; i < 4; i++)
                #pragma unroll
                for (int j = 0; j < 4; j++)
                    pv[i][j] += p[i] * v[j];
        }
        float al[4];
        #pragma unroll
        for (int i = 0; i < 4; i++) al[i] = arow[ty * 4 + i];
        #pragma unroll
        for (int i = 0; i < 4; i++)
            #pragma unroll
            for (int j = 0; j < 4; j++)
                oacc[i][j] = oacc[i][j] * al[i] + pv[i][j];
        __syncthreads();
    }

    #pragma unroll
    for (int i = 0; i < 4; i++) {
        const float linv = 1.f / lrow[ty * 4 + i];
        const int m = qt * QT + ty * 4 + i;
        #pragma unroll
        for (int j = 0; j < 4; j++)
            o[(size_t)m * O_DIM + h * HD + tx * 4 + j] = oacc[i][j] * linv;
    }
}

// ---------------------------------------------------------------------------
// Clamped SwiGLU
// ---------------------------------------------------------------------------
__global__ __launch_bounds__(256) void act_kernel(
    const float* __restrict__ u, float* __restrict__ act)
{
    const int idx = blockIdx.x * 256 + threadIdx.x;
    if (idx >= T_TOK * INTER) return;
    const int row = idx / INTER, col = idx - row * INTER;
    float g   = u[(size_t)row * U_DIM + 2 * col];
    float lin = u[(size_t)row * U_DIM + 2 * col + 1];
    g   = fminf(g, 7.f);
    lin = fminf(fmaxf(lin, -7.f), 7.f);
    const float sg = 1.f / (1.f + expf(-1.702f * g));
    act[idx] = g * sg * (lin + 1.f);
}

// ---------------------------------------------------------------------------
// Launch
// ---------------------------------------------------------------------------
static inline int cdiv_ll(long long a, int b) { return (int)((a + b - 1) / b); }

extern "C" void kernel_launch(void* const* d_in, const int* in_sizes, int n_in,
                              void* d_out, int out_size)
{
    const float* x        = (const float*)d_in[0];
    const float* an_scale = (const float*)d_in[1];
    const float* wqkv     = (const float*)d_in[2];
    const float* bqkv     = (const float*)d_in[3];
    const float* wout     = (const float*)d_in[4];
    const float* bout     = (const float*)d_in[5];
    const float* mn_scale = (const float*)d_in[6];
    const float* w1       = (const float*)d_in[7];
    const float* b1       = (const float*)d_in[8];
    const float* w2       = (const float*)d_in[9];
    const float* b2       = (const float*)d_in[10];
    float* out = (float*)d_out;

    static float *t_p = nullptr, *qkv_p, *o_p, *h_p, *u_p, *act_p;
    static __nv_bfloat16 *w2qkv_p, *w2out_p, *w2up_p, *w2dn_p, *a2_p;
    if (!t_p) {
        cudaGetSymbolAddress((void**)&t_p,    g_t);
        cudaGetSymbolAddress((void**)&qkv_p,  g_qkv);
        cudaGetSymbolAddress((void**)&o_p,    g_o);
        cudaGetSymbolAddress((void**)&h_p,    g_h);
        cudaGetSymbolAddress((void**)&u_p,    g_u);
        cudaGetSymbolAddress((void**)&act_p,  g_act);
        cudaGetSymbolAddress((void**)&w2qkv_p, g_w2_qkv);
        cudaGetSymbolAddress((void**)&w2out_p, g_w2_out);
        cudaGetSymbolAddress((void**)&w2up_p,  g_w2_up);
        cudaGetSymbolAddress((void**)&w2dn_p,  g_w2_dn);
        cudaGetSymbolAddress((void**)&a2_p,    g_a2);
    }
    cudaFuncSetAttribute(attn_kernel,
                         cudaFuncAttributeMaxDynamicSharedMemorySize, ATTN_SMEM);
    cudaFuncSetAttribute(mma_gemm<false>,
                         cudaFuncAttributeMaxDynamicSharedMemorySize, GSMEM_TOTAL);
    cudaFuncSetAttribute(mma_gemm<true>,
                         cudaFuncAttributeMaxDynamicSharedMemorySize, GSMEM_TOTAL);

    // Weight splits (every launch; deterministic)
    convert_split_kernel<<<cdiv_ll((long long)QKV_DIM * HID / 4, 256), 256>>>(
        wqkv, w2qkv_p, QKV_DIM, HID, QKV_DIM);
    convert_split_kernel<<<cdiv_ll((long long)NPAD_2880 * O_DIM / 4, 256), 256>>>(
        wout, w2out_p, HID, O_DIM, NPAD_2880);
    convert_split_kernel<<<cdiv_ll((long long)U_DIM * HID / 4, 256), 256>>>(
        w1, w2up_p, U_DIM, HID, U_DIM);
    convert_split_kernel<<<cdiv_ll((long long)NPAD_2880 * INTER / 4, 256), 256>>>(
        w2, w2dn_p, HID, INTER, NPAD_2880);

    // 1) attn rmsnorm
    rmsnorm_kernel<<<T_TOK, 256>>>(x, an_scale, t_p);

    // 2) QKV GEMM
    convert_split_kernel<<<cdiv_ll((long long)T_TOK * HID / 4, 256), 256>>>(
        t_p, a2_p, T_TOK, HID, T_TOK);
    {
        dim3 grid(T_TOK / 128, QKV_DIM / 128);
        mma_gemm<false><<<grid, 256, GSMEM_TOTAL>>>(a2_p, w2qkv_p, bqkv, nullptr,
                                                    qkv_p, HID, QKV_DIM);
    }

    // 3) RoPE
    {
        dim3 grid(T_TOK, NH + KVH);
        rope_kernel<<<grid, 32>>>(qkv_p);
    }

    // 4) attention
    {
        dim3 grid(T_TOK / QT, NH);
        attn_kernel<<<grid, 256, ATTN_SMEM>>>(qkv_p, o_p);
    }

    // 5) out GEMM + residual
    convert_split_kernel<<<cdiv_ll((long long)T_TOK * O_DIM / 4, 256), 256>>>(
        o_p, a2_p, T_TOK, O_DIM, T_TOK);
    {
        dim3 grid(T_TOK / 128, NPAD_2880 / 128);
        mma_gemm<true><<<grid, 256, GSMEM_TOTAL>>>(a2_p, w2out_p, bout, x,
                                                   h_p, O_DIM, HID);
    }

    // 6) mlp rmsnorm
    rmsnorm_kernel<<<T_TOK, 256>>>(h_p, mn_scale, t_p);

    // 7) MLP up GEMM
    convert_split_kernel<<<cdiv_ll((long long)T_TOK * HID / 4, 256), 256>>>(
        t_p, a2_p, T_TOK, HID, T_TOK);
    {
        dim3 grid(T_TOK / 128, U_DIM / 128);
        mma_gemm<false><<<grid, 256, GSMEM_TOTAL>>>(a2_p, w2up_p, b1, nullptr,
                                                    u_p, HID, U_DIM);
    }

    // 8) activation
    act_kernel<<<(T_TOK * INTER + 255) / 256, 256>>>(u_p, act_p);

    // 9) MLP down GEMM + residual -> out
    convert_split_kernel<<<cdiv_ll((long long)T_TOK * INTER / 4, 256), 256>>>(
        act_p, a2_p, T_TOK, INTER, T_TOK);
    {
        dim3 grid(T_TOK / 128, NPAD_2880 / 128);
        mma_gemm<true><<<grid, 256, GSMEM_TOTAL>>>(a2_p, w2dn_p, b2, h_p,
                                                   out, INTER, HID);
    }
}

// round 4
// speedup vs baseline: 1.6870x; 1.3699x over previous
#include <cuda_runtime.h>
#include <cuda_bf16.h>
#include <math.h>
#include <stdint.h>

// ---------------------------------------------------------------------------
// Problem constants
// ---------------------------------------------------------------------------
#define T_TOK   1024
#define HID     2880
#define NH      64
#define KVH     8
#define HD      64
#define INTER   2880
#define QKV_DIM (HD*(NH+2*KVH))      // 5120
#define O_DIM   (NH*HD)              // 4096
#define U_DIM   (2*INTER)            // 5760
#define SM_SCALE 0.125f
#define EPSF    1e-5f

#define NPAD_OUT 3072                // 12*256
#define NPAD_UP  5888                // 23*256
#define NPAD_DN  3072                // 12*256

// ---------------------------------------------------------------------------
// Scratch (__device__ globals; allocation-free)
// ---------------------------------------------------------------------------
__device__ float g_t  [T_TOK * HID];
__device__ float g_qkv[T_TOK * QKV_DIM];
__device__ float g_o  [T_TOK * O_DIM];
__device__ float g_h  [T_TOK * HID];
__device__ float g_u  [T_TOK * U_DIM];
__device__ float g_act[T_TOK * INTER];

// split-bf16 buffers: row layout [hi(0..K-1) | lo(K..2K-1)], row stride 2K
__device__ __align__(256) __nv_bfloat16 g_w2_qkv[QKV_DIM * 2 * HID];
__device__ __align__(256) __nv_bfloat16 g_w2_out[NPAD_OUT * 2 * O_DIM];
__device__ __align__(256) __nv_bfloat16 g_w2_up [NPAD_UP  * 2 * HID];
__device__ __align__(256) __nv_bfloat16 g_w2_dn [NPAD_DN  * 2 * INTER];
__device__ __align__(256) __nv_bfloat16 g_a2    [T_TOK * 2 * O_DIM];

// ---------------------------------------------------------------------------
// PTX helpers (base-target-safe: cp.async / ldmatrix / mma.sync only)
// ---------------------------------------------------------------------------
__device__ __forceinline__ uint32_t smem_u32(const void* p) {
    uint32_t a;
    asm("{ .reg .u64 t; cvta.to.shared.u64 t, %1; cvt.u32.u64 %0, t; }" : "=r"(a) : "l"(p));
    return a;
}
__device__ __forceinline__ void cp16(uint32_t dst, const void* src) {
    asm volatile("cp.async.cg.shared.global [%0], [%1], 16;" :: "r"(dst), "l"(src));
}
__device__ __forceinline__ void cp_commit() {
    asm volatile("cp.async.commit_group;" ::: "memory");
}
__device__ __forceinline__ void cp_wait1() {
    asm volatile("cp.async.wait_group 1;" ::: "memory");
}
__device__ __forceinline__ void cp_wait0() {
    asm volatile("cp.async.wait_group 0;" ::: "memory");
}
__device__ __forceinline__ void ldmatrix_x4(uint32_t& r0, uint32_t& r1,
                                            uint32_t& r2, uint32_t& r3, uint32_t addr) {
    asm volatile("ldmatrix.sync.aligned.m8n8.x4.shared.b16 {%0,%1,%2,%3}, [%4];"
        : "=r"(r0), "=r"(r1), "=r"(r2), "=r"(r3) : "r"(addr));
}
__device__ __forceinline__ void mma_bf16(float& c0, float& c1, float& c2, float& c3,
                                         uint32_t a0, uint32_t a1, uint32_t a2, uint32_t a3,
                                         uint32_t b0, uint32_t b1) {
    asm volatile("mma.sync.aligned.m16n8k16.row.col.f32.bf16.bf16.f32 "
        "{%0,%1,%2,%3}, {%4,%5,%6,%7}, {%8,%9}, {%0,%1,%2,%3};"
        : "+f"(c0), "+f"(c1), "+f"(c2), "+f"(c3)
        : "r"(a0), "r"(a1), "r"(a2), "r"(a3), "r"(b0), "r"(b1));
}

// ---------------------------------------------------------------------------
// fp32 -> [hi | lo] bf16 split conversion. Row stride 2K; rows >= Nrows zeroed.
// ---------------------------------------------------------------------------
__global__ __launch_bounds__(256) void convert_split_kernel(
    const float* __restrict__ X, __nv_bfloat16* __restrict__ X2,
    int Nrows, int K, int Npad)
{
    const long long idx = (long long)blockIdx.x * 256 + threadIdx.x;
    const int kq = K >> 2;
    const long long total = (long long)Npad * kq;
    if (idx >= total) return;
    const int n = (int)(idx / kq);
    const int k = (int)(idx - (long long)n * kq) * 4;
    float4 v = make_float4(0.f, 0.f, 0.f, 0.f);
    if (n < Nrows) v = *(const float4*)(X + (size_t)n * K + k);
    __nv_bfloat16 hx = __float2bfloat16(v.x);
    __nv_bfloat16 hy = __float2bfloat16(v.y);
    __nv_bfloat16 hz = __float2bfloat16(v.z);
    __nv_bfloat16 hw = __float2bfloat16(v.w);
    float lx = v.x - __bfloat162float(hx);
    float ly = v.y - __bfloat162float(hy);
    float lz = v.z - __bfloat162float(hz);
    float lw = v.w - __bfloat162float(hw);
    __nv_bfloat16* row = X2 + (size_t)n * 2 * K;
    __nv_bfloat162* ph = (__nv_bfloat162*)(row + k);
    ph[0] = __halves2bfloat162(hx, hy);
    ph[1] = __halves2bfloat162(hz, hw);
    __nv_bfloat162* pl = (__nv_bfloat162*)(row + K + k);
    pl[0] = __floats2bfloat162_rn(lx, ly);
    pl[1] = __floats2bfloat162_rn(lz, lw);
}

// ---------------------------------------------------------------------------
// Split-bf16 GEMM via mma.sync: C[m,n] = sum_k A[m,k]*W[n,k] (+bias +res)
// 128x256 CTA tile, BK=64 bf16, double-buffered cp.async.
// 8 warps as 2(m) x 4(n); warp tile 64x64; m16n8k16 bf16 HMMA.
// smem row stride 144B -> conflict-free ldmatrix + contiguous cp.async.
// ---------------------------------------------------------------------------
#define KSTRIDE_B 144
#define ATILE_B  (128 * KSTRIDE_B)    // 18432
#define BTILE_B  (256 * KSTRIDE_B)    // 36864
#define GSMEM_TOTAL (2 * ATILE_B + 2 * BTILE_B)   // 110592

__device__ __forceinline__ void fill_tiles_mma(
    uint32_t aT, uint32_t bT,
    const __nv_bfloat16* __restrict__ A2, const __nv_bfloat16* __restrict__ W2,
    int Kp, int m0, int n0, int ka, int kw, int tid)
{
    #pragma unroll
    for (int i = 0; i < 4; i++) {
        int q = tid + 256 * i;
        int r = q >> 3, c = q & 7;
        cp16(aT + r * KSTRIDE_B + c * 16, A2 + (size_t)(m0 + r) * Kp + ka + c * 8);
    }
    #pragma unroll
    for (int i = 0; i < 8; i++) {
        int q = tid + 256 * i;
        int r = q >> 3, c = q & 7;
        cp16(bT + r * KSTRIDE_B + c * 16, W2 + (size_t)(n0 + r) * Kp + kw + c * 8);
    }
}

template<bool RES>
__global__ __launch_bounds__(256) void mma_gemm(
    const __nv_bfloat16* __restrict__ A2, const __nv_bfloat16* __restrict__ W2,
    const float* __restrict__ bias, const float* __restrict__ res,
    float* __restrict__ C, int K, int Nout)
{
    extern __shared__ char smem[];
    const uint32_t sbase = smem_u32(smem);
    const uint32_t tA[2] = { sbase,                sbase + ATILE_B };
    const uint32_t tB[2] = { sbase + 2 * ATILE_B,  sbase + 2 * ATILE_B + BTILE_B };

    const int tid  = threadIdx.x;
    const int wid  = tid >> 5;
    const int lane = tid & 31;
    const int wm   = wid >> 2;        // 0..1  (64 rows each)
    const int wn   = wid & 3;         // 0..3  (64 cols each)
    const int m0 = blockIdx.x * 128;
    const int n0 = blockIdx.y * 256;
    const int Kp = 2 * K;
    const int NCseg = K >> 6;
    const int NC = 3 * NCseg;

    const uint32_t aOff = (uint32_t)((wm * 64 + (lane & 15)) * KSTRIDE_B + (lane >> 4) * 16);
    const uint32_t bOff = (uint32_t)((wn * 64 + (lane & 7) + ((lane >> 4) & 1) * 8) * KSTRIDE_B
                                     + ((lane >> 3) & 1) * 16);

    float acc[4][8][4];
    #pragma unroll
    for (int i = 0; i < 4; i++)
        #pragma unroll
        for (int j = 0; j < 8; j++)
            #pragma unroll
            for (int q = 0; q < 4; q++) acc[i][j][q] = 0.f;

    fill_tiles_mma(tA[0], tB[0], A2, W2, Kp, m0, n0, 0, 0, tid);
    cp_commit();

    for (int c = 0; c < NC; c++) {
        const int b = c & 1;
        if (c + 1 < NC) {
            const int nb = (c + 1) & 1;
            const int cn = c + 1;
            const int seg = cn / NCseg;
            const int kk = (cn - seg * NCseg) << 6;
            const int ka = (seg < 2) ? kk : K + kk;
            const int kw = (seg == 1) ? K + kk : kk;
            fill_tiles_mma(tA[nb], tB[nb], A2, W2, Kp, m0, n0, ka, kw, tid);
            cp_commit();
            cp_wait1();
        } else {
            cp_wait0();
        }
        __syncthreads();

        #pragma unroll
        for (int ks = 0; ks < 4; ks++) {
            const uint32_t kb = (uint32_t)(ks * 32);
            uint32_t a[4][4];
            #pragma unroll
            for (int mf = 0; mf < 4; mf++)
                ldmatrix_x4(a[mf][0], a[mf][1], a[mf][2], a[mf][3],
                            tA[b] + aOff + mf * 16 * KSTRIDE_B + kb);
            uint32_t bb[8][2];
            #pragma unroll
            for (int bf = 0; bf < 4; bf++) {
                uint32_t r0, r1, r2, r3;
                ldmatrix_x4(r0, r1, r2, r3,
                            tB[b] + bOff + bf * 16 * KSTRIDE_B + kb);
                bb[bf * 2 + 0][0] = r0; bb[bf * 2 + 0][1] = r1;
                bb[bf * 2 + 1][0] = r2; bb[bf * 2 + 1][1] = r3;
            }
            #pragma unroll
            for (int mf = 0; mf < 4; mf++)
                #pragma unroll
                for (int nf = 0; nf < 8; nf++)
                    mma_bf16(acc[mf][nf][0], acc[mf][nf][1],
                             acc[mf][nf][2], acc[mf][nf][3],
                             a[mf][0], a[mf][1], a[mf][2], a[mf][3],
                             bb[nf][0], bb[nf][1]);
        }
        __syncthreads();
    }

    // Epilogue
    const int g = lane >> 2;
    const int t = lane & 3;
    #pragma unroll
    for (int nf = 0; nf < 8; nf++) {
        const int col = n0 + wn * 64 + nf * 8 + t * 2;
        if (col >= Nout) continue;
        const float bx = bias[col], by = bias[col + 1];
        #pragma unroll
        for (int mf = 0; mf < 4; mf++) {
            const int r0 = m0 + wm * 64 + mf * 16 + g;
            float2 v0 = make_float2(acc[mf][nf][0] + bx, acc[mf][nf][1] + by);
            float2 v1 = make_float2(acc[mf][nf][2] + bx, acc[mf][nf][3] + by);
            if (RES) {
                const float2 q0 = *(const float2*)(res + (size_t)r0 * Nout + col);
                const float2 q1 = *(const float2*)(res + (size_t)(r0 + 8) * Nout + col);
                v0.x += q0.x; v0.y += q0.y; v1.x += q1.x; v1.y += q1.y;
            }
            *(float2*)(C + (size_t)r0 * Nout + col) = v0;
            *(float2*)(C + (size_t)(r0 + 8) * Nout + col) = v1;
        }
    }
}

// ---------------------------------------------------------------------------
// RMSNorm
// ---------------------------------------------------------------------------
__global__ __launch_bounds__(256) void rmsnorm_kernel(
    const float* __restrict__ x, const float* __restrict__ scale,
    float* __restrict__ out)
{
    const int row = blockIdx.x;
    const float* xr = x + (size_t)row * HID;
    float s = 0.f;
    for (int i = threadIdx.x; i < HID; i += 256) { float v = xr[i]; s += v * v; }
    __shared__ float red[256];
    red[threadIdx.x] = s;
    __syncthreads();
    for (int off = 128; off > 0; off >>= 1) {
        if (threadIdx.x < off) red[threadIdx.x] += red[threadIdx.x + off];
        __syncthreads();
    }
    const float inv = rsqrtf(red[0] / (float)HID + EPSF);
    float* orow = out + (size_t)row * HID;
    for (int i = threadIdx.x; i < HID; i += 256)
        orow[i] = xr[i] * inv * scale[i];
}

// ---------------------------------------------------------------------------
// RoPE
// ---------------------------------------------------------------------------
__global__ void rope_kernel(float* __restrict__ qkv)
{
    const int t = blockIdx.x;
    const int head = blockIdx.y;
    const int i = threadIdx.x;

    float* base;
    if (head < NH) base = qkv + (size_t)t * QKV_DIM + head * HD;
    else           base = qkv + (size_t)t * QKV_DIM + NH * HD + (head - NH) * HD;

    const float PI = 3.14159265358979323846f;
    const float rope_base = 150000.f;
    const float freq = powf(rope_base, (float)i / 32.f);
    const float conc = 0.1f * logf(32.f) + 1.f;
    const float lg = logf(rope_base);
    const float low  = 32.f * logf(4096.f / (32.f * 2.f * PI)) / lg;
    const float high = 32.f * logf(4096.f / (2.f * PI)) / lg;
    const float interp = 1.f / (32.f * freq);
    const float extrap = 1.f / freq;
    float ramp = ((float)i - low) / (high - low);
    ramp = fminf(fmaxf(ramp, 0.f), 1.f);
    const float mask = 1.f - ramp;
    const float invf = interp * (1.f - mask) + extrap * mask;
    const float ang = (float)t * invf;
    const float c = cosf(ang) * conc;
    const float s = sinf(ang) * conc;

    const float x1 = base[i];
    const float x2 = base[i + 32];
    base[i]      = x1 * c - x2 * s;
    base[i + 32] = x2 * c + x1 * s;
}

// ---------------------------------------------------------------------------
// Causal GQA flash attention (fp32), parallel softmax across all 256 threads
// ---------------------------------------------------------------------------
#define QT 64
#define ATTN_SMEM ((4 * 64 * 65 + 3 * 64 + 2 * 256) * (int)sizeof(float))

__global__ __launch_bounds__(256) void attn_kernel(
    const float* __restrict__ qkv, float* __restrict__ o)
{
    extern __shared__ float sm[];
    float* Qs   = sm;
    float* Ks   = Qs + 64 * 65;
    float* Vs   = Ks + 64 * 65;
    float* Ss   = Vs + 64 * 65;
    float* mrow = Ss + 64 * 65;
    float* lrow = mrow + 64;
    float* arow = lrow + 64;
    float* pm   = arow + 64;      // [4][64]
    float* ps   = pm + 256;       // [4][64]

    const int qt = blockIdx.x;
    const int h  = blockIdx.y;
    const int kh = h >> 3;
    const int tid = threadIdx.x;
    const int ty = tid >> 4, tx = tid & 15;
    const int sr = tid & 63;      // softmax row
    const int sq = tid >> 6;      // softmax quarter 0..3

    for (int i = tid; i < 64 * 64; i += 256) {
        int r = i >> 6, d = i & 63;
        Qs[r * 65 + d] = qkv[(size_t)(qt * QT + r) * QKV_DIM + h * HD + d];
    }
    if (tid < 64) { mrow[tid] = -1e30f; lrow[tid] = 0.f; }
    float oacc[4][4];
    #pragma unroll
    for (int i = 0; i < 4; i++)
        #pragma unroll
        for (int j = 0; j < 4; j++) oacc[i][j] = 0.f;
    __syncthreads();

    for (int kt = 0; kt <= qt; kt++) {
        for (int i = tid; i < 64 * 64; i += 256) {
            int r = i >> 6, d = i & 63;
            size_t base = (size_t)(kt * QT + r) * QKV_DIM;
            Ks[r * 65 + d] = qkv[base + NH * HD + kh * HD + d];
            Vs[r * 65 + d] = qkv[base + (NH + KVH) * HD + kh * HD + d];
        }
        __syncthreads();

        // S = Q K^T * scale
        float acc[4][4];
        #pragma unroll
        for (int i = 0; i < 4; i++)
            #pragma unroll
            for (int j = 0; j < 4; j++) acc[i][j] = 0.f;
        #pragma unroll 8
        for (int d = 0; d < 64; d++) {
            float a[4], b[4];
            #pragma unroll
            for (int i = 0; i < 4; i++) a[i] = Qs[(ty * 4 + i) * 65 + d];
            #pragma unroll
            for (int j = 0; j < 4; j++) b[j] = Ks[(tx * 4 + j) * 65 + d];
            #pragma unroll
            for (int i = 0; i < 4; i++)
                #pragma unroll
                for (int j = 0; j < 4; j++)
                    acc[i][j] += a[i] * b[j];
        }
        #pragma unroll
        for (int i = 0; i < 4; i++)
            #pragma unroll
            for (int j = 0; j < 4; j++)
                Ss[(ty * 4 + i) * 65 + tx * 4 + j] = acc[i][j] * SM_SCALE;
        __syncthreads();

        // parallel online softmax: 4 threads per row, 16 cols each
        {
            const int cmax = (kt == qt) ? (sr + 1) : 64;
            const int c0 = sq * 16;
            float mx = -1e30f;
            #pragma unroll
            for (int c = c0; c < c0 + 16; c++)
                if (c < cmax) mx = fmaxf(mx, Ss[sr * 65 + c]);
            pm[sq * 64 + sr] = mx;
            __syncthreads();
            const float mold = mrow[sr];
            const float mfin = fmaxf(mold,
                fmaxf(fmaxf(pm[sr], pm[64 + sr]), fmaxf(pm[128 + sr], pm[192 + sr])));
            float sum = 0.f;
            #pragma unroll
            for (int c = c0; c < c0 + 16; c++) {
                float p = (c < cmax) ? __expf(Ss[sr * 65 + c] - mfin) : 0.f;
                Ss[sr * 65 + c] = p;
                sum += p;
            }
            ps[sq * 64 + sr] = sum;
            __syncthreads();
            if (sq == 0) {
                const float alpha = __expf(mold - mfin);
                mrow[sr] = mfin;
                lrow[sr] = lrow[sr] * alpha
                         + ps[sr] + ps[64 + sr] + ps[128 + sr] + ps[192 + sr];
                arow[sr] = alpha;
            }
            __syncthreads();
        }

        // O = O*alpha + P @ V
        float pv[4][4];
        #pragma unroll
        for (int i = 0; i < 4; i++)
            #pragma unroll
            for (int j = 0; j < 4; j++) pv[i][j] = 0.f;
        #pragma unroll 8
        for (int c = 0; c < 64; c++) {
            float p[4], v[4];
            #pragma unroll
            for (int i = 0; i < 4; i++) p[i] = Ss[(ty * 4 + i) * 65 + c];
            #pragma unroll
            for (int j = 0; j < 4; j++) v[j] = Vs[c * 65 + tx * 4 + j];
            #pragma unroll
            for (int i = 0; i < 4; i++)
                #pragma unroll
                for (int j = 0; j < 4; j++)
                    pv[i][j] += p[i] * v[j];
        }
        float al[4];
        #pragma unroll
        for (int i = 0; i < 4; i++) al[i] = arow[ty * 4 + i];
        #pragma unroll
        for (int i = 0; i < 4; i++)
            #pragma unroll
            for (int j = 0; j < 4; j++)
                oacc[i][j] = oacc[i][j] * al[i] + pv[i][j];
        __syncthreads();
    }

    #pragma unroll
    for (int i = 0; i < 4; i++) {
        const float linv = 1.f / lrow[ty * 4 + i];
        const int m = qt * QT + ty * 4 + i;
        #pragma unroll
        for (int j = 0; j < 4; j++)
            o[(size_t)m * O_DIM + h * HD + tx * 4 + j] = oacc[i][j] * linv;
    }
}

// ---------------------------------------------------------------------------
// Clamped SwiGLU
// ---------------------------------------------------------------------------
__global__ __launch_bounds__(256) void act_kernel(
    const float* __restrict__ u, float* __restrict__ act)
{
    const int idx = blockIdx.x * 256 + threadIdx.x;
    if (idx >= T_TOK * INTER) return;
    const int row = idx / INTER, col = idx - row * INTER;
    float g   = u[(size_t)row * U_DIM + 2 * col];
    float lin = u[(size_t)row * U_DIM + 2 * col + 1];
    g   = fminf(g, 7.f);
    lin = fminf(fmaxf(lin, -7.f), 7.f);
    const float sg = 1.f / (1.f + __expf(-1.702f * g));
    act[idx] = g * sg * (lin + 1.f);
}

// ---------------------------------------------------------------------------
// Launch
// ---------------------------------------------------------------------------
static inline int cdiv_ll(long long a, int b) { return (int)((a + b - 1) / b); }

extern "C" void kernel_launch(void* const* d_in, const int* in_sizes, int n_in,
                              void* d_out, int out_size)
{
    const float* x        = (const float*)d_in[0];
    const float* an_scale = (const float*)d_in[1];
    const float* wqkv     = (const float*)d_in[2];
    const float* bqkv     = (const float*)d_in[3];
    const float* wout     = (const float*)d_in[4];
    const float* bout     = (const float*)d_in[5];
    const float* mn_scale = (const float*)d_in[6];
    const float* w1       = (const float*)d_in[7];
    const float* b1       = (const float*)d_in[8];
    const float* w2       = (const float*)d_in[9];
    const float* b2       = (const float*)d_in[10];
    float* out = (float*)d_out;

    static float *t_p = nullptr, *qkv_p, *o_p, *h_p, *u_p, *act_p;
    static __nv_bfloat16 *w2qkv_p, *w2out_p, *w2up_p, *w2dn_p, *a2_p;
    if (!t_p) {
        cudaGetSymbolAddress((void**)&t_p,    g_t);
        cudaGetSymbolAddress((void**)&qkv_p,  g_qkv);
        cudaGetSymbolAddress((void**)&o_p,    g_o);
        cudaGetSymbolAddress((void**)&h_p,    g_h);
        cudaGetSymbolAddress((void**)&u_p,    g_u);
        cudaGetSymbolAddress((void**)&act_p,  g_act);
        cudaGetSymbolAddress((void**)&w2qkv_p, g_w2_qkv);
        cudaGetSymbolAddress((void**)&w2out_p, g_w2_out);
        cudaGetSymbolAddress((void**)&w2up_p,  g_w2_up);
        cudaGetSymbolAddress((void**)&w2dn_p,  g_w2_dn);
        cudaGetSymbolAddress((void**)&a2_p,    g_a2);
    }
    cudaFuncSetAttribute(attn_kernel,
                         cudaFuncAttributeMaxDynamicSharedMemorySize, ATTN_SMEM);
    cudaFuncSetAttribute(mma_gemm<false>,
                         cudaFuncAttributeMaxDynamicSharedMemorySize, GSMEM_TOTAL);
    cudaFuncSetAttribute(mma_gemm<true>,
                         cudaFuncAttributeMaxDynamicSharedMemorySize, GSMEM_TOTAL);

    // Weight splits (every launch; deterministic)
    convert_split_kernel<<<cdiv_ll((long long)QKV_DIM * HID / 4, 256), 256>>>(
        wqkv, w2qkv_p, QKV_DIM, HID, QKV_DIM);
    convert_split_kernel<<<cdiv_ll((long long)NPAD_OUT * O_DIM / 4, 256), 256>>>(
        wout, w2out_p, HID, O_DIM, NPAD_OUT);
    convert_split_kernel<<<cdiv_ll((long long)NPAD_UP * HID / 4, 256), 256>>>(
        w1, w2up_p, U_DIM, HID, NPAD_UP);
    convert_split_kernel<<<cdiv_ll((long long)NPAD_DN * INTER / 4, 256), 256>>>(
        w2, w2dn_p, HID, INTER, NPAD_DN);

    // 1) attn rmsnorm
    rmsnorm_kernel<<<T_TOK, 256>>>(x, an_scale, t_p);

    // 2) QKV GEMM
    convert_split_kernel<<<cdiv_ll((long long)T_TOK * HID / 4, 256), 256>>>(
        t_p, a2_p, T_TOK, HID, T_TOK);
    {
        dim3 grid(T_TOK / 128, QKV_DIM / 256);
        mma_gemm<false><<<grid, 256, GSMEM_TOTAL>>>(a2_p, w2qkv_p, bqkv, nullptr,
                                                    qkv_p, HID, QKV_DIM);
    }

    // 3) RoPE
    {
        dim3 grid(T_TOK, NH + KVH);
        rope_kernel<<<grid, 32>>>(qkv_p);
    }

    // 4) attention
    {
        dim3 grid(T_TOK / QT, NH);
        attn_kernel<<<grid, 256, ATTN_SMEM>>>(qkv_p, o_p);
    }

    // 5) out GEMM + residual
    convert_split_kernel<<<cdiv_ll((long long)T_TOK * O_DIM / 4, 256), 256>>>(
        o_p, a2_p, T_TOK, O_DIM, T_TOK);
    {
        dim3 grid(T_TOK / 128, NPAD_OUT / 256);
        mma_gemm<true><<<grid, 256, GSMEM_TOTAL>>>(a2_p, w2out_p, bout, x,
                                                   h_p, O_DIM, HID);
    }

    // 6) mlp rmsnorm
    rmsnorm_kernel<<<T_TOK, 256>>>(h_p, mn_scale, t_p);

    // 7) MLP up GEMM
    convert_split_kernel<<<cdiv_ll((long long)T_TOK * HID / 4, 256), 256>>>(
        t_p, a2_p, T_TOK, HID, T_TOK);
    {
        dim3 grid(T_TOK / 128, NPAD_UP / 256);
        mma_gemm<false><<<grid, 256, GSMEM_TOTAL>>>(a2_p, w2up_p, b1, nullptr,
                                                    u_p, HID, U_DIM);
    }

    // 8) activation
    act_kernel<<<(T_TOK * INTER + 255) / 256, 256>>>(u_p, act_p);

    // 9) MLP down GEMM + residual -> out
    convert_split_kernel<<<cdiv_ll((long long)T_TOK * INTER / 4, 256), 256>>>(
        act_p, a2_p, T_TOK, INTER, T_TOK);
    {
        dim3 grid(T_TOK / 128, NPAD_DN / 256);
        mma_gemm<true><<<grid, 256, GSMEM_TOTAL>>>(a2_p, w2dn_p, b2, h_p,
                                                   out, INTER, HID);
    }
}

// round 5
// speedup vs baseline: 1.8516x; 1.0976x over previous
#include <cuda_runtime.h>
#include <cuda_bf16.h>
#include <math.h>
#include <stdint.h>

// ---------------------------------------------------------------------------
// Problem constants
// ---------------------------------------------------------------------------
#define T_TOK   1024
#define HID     2880
#define NH      64
#define KVH     8
#define HD      64
#define INTER   2880
#define QKV_DIM (HD*(NH+2*KVH))      // 5120
#define O_DIM   (NH*HD)              // 4096
#define U_DIM   (2*INTER)            // 5760
#define SM_SCALE 0.125f
#define EPSF    1e-5f

#define NPAD_OUT 3072
#define NPAD_UP  5888
#define NPAD_DN  3072

// ---------------------------------------------------------------------------
// Scratch
// ---------------------------------------------------------------------------
__device__ float g_qkv[T_TOK * QKV_DIM];
__device__ float g_h  [T_TOK * HID];
__device__ float g_u  [T_TOK * U_DIM];

__device__ __align__(256) __nv_bfloat16 g_w2_qkv[QKV_DIM * 2 * HID];
__device__ __align__(256) __nv_bfloat16 g_w2_out[NPAD_OUT * 2 * O_DIM];
__device__ __align__(256) __nv_bfloat16 g_w2_up [NPAD_UP  * 2 * HID];
__device__ __align__(256) __nv_bfloat16 g_w2_dn [NPAD_DN  * 2 * INTER];
__device__ __align__(256) __nv_bfloat16 g_a2    [T_TOK * 2 * O_DIM];

// ---------------------------------------------------------------------------
// PTX helpers
// ---------------------------------------------------------------------------
__device__ __forceinline__ uint32_t smem_u32(const void* p) {
    uint32_t a;
    asm("{ .reg .u64 t; cvta.to.shared.u64 t, %1; cvt.u32.u64 %0, t; }" : "=r"(a) : "l"(p));
    return a;
}
__device__ __forceinline__ void cp16(uint32_t dst, const void* src) {
    asm volatile("cp.async.cg.shared.global [%0], [%1], 16;" :: "r"(dst), "l"(src));
}
__device__ __forceinline__ void cp_commit() {
    asm volatile("cp.async.commit_group;" ::: "memory");
}
__device__ __forceinline__ void cp_wait1() {
    asm volatile("cp.async.wait_group 1;" ::: "memory");
}
__device__ __forceinline__ void cp_wait0() {
    asm volatile("cp.async.wait_group 0;" ::: "memory");
}
__device__ __forceinline__ void ldmatrix_x4(uint32_t& r0, uint32_t& r1,
                                            uint32_t& r2, uint32_t& r3, uint32_t addr) {
    asm volatile("ldmatrix.sync.aligned.m8n8.x4.shared.b16 {%0,%1,%2,%3}, [%4];"
        : "=r"(r0), "=r"(r1), "=r"(r2), "=r"(r3) : "r"(addr));
}
__device__ __forceinline__ void mma_bf16(float& c0, float& c1, float& c2, float& c3,
                                         uint32_t a0, uint32_t a1, uint32_t a2, uint32_t a3,
                                         uint32_t b0, uint32_t b1) {
    asm volatile("mma.sync.aligned.m16n8k16.row.col.f32.bf16.bf16.f32 "
        "{%0,%1,%2,%3}, {%4,%5,%6,%7}, {%8,%9}, {%0,%1,%2,%3};"
        : "+f"(c0), "+f"(c1), "+f"(c2), "+f"(c3)
        : "r"(a0), "r"(a1), "r"(a2), "r"(a3), "r"(b0), "r"(b1));
}
__device__ __forceinline__ void mma_tf32(float* c, const uint32_t* a, const uint32_t* b) {
    asm volatile("mma.sync.aligned.m16n8k8.row.col.f32.tf32.tf32.f32 "
        "{%0,%1,%2,%3}, {%4,%5,%6,%7}, {%8,%9}, {%0,%1,%2,%3};"
        : "+f"(c[0]), "+f"(c[1]), "+f"(c[2]), "+f"(c[3])
        : "r"(a[0]), "r"(a[1]), "r"(a[2]), "r"(a[3]), "r"(b[0]), "r"(b[1]));
}
__device__ __forceinline__ float tf32r(float x) {
    uint32_t o;
    asm("cvt.rna.tf32.f32 %0, %1;" : "=r"(o) : "f"(x));
    return __uint_as_float(o);
}

// FMA-pipe exp (magic-number 2^n split + deg-5 Taylor on [-0.5,0.5], rel err ~2e-6)
__device__ __forceinline__ float fast_exp(float x) {
    x = fmaxf(x, -80.f);
    const float y = x * 1.4426950408889634f;
    const float fn = y + 12582912.f;
    const int ni = __float_as_int(fn) - 0x4B400000;
    const float f = y - (fn - 12582912.f);
    float p = 1.3333558146e-3f;
    p = fmaf(p, f, 9.6181291076e-3f);
    p = fmaf(p, f, 5.5504108664e-2f);
    p = fmaf(p, f, 2.4022650696e-1f);
    p = fmaf(p, f, 6.9314718056e-1f);
    p = fmaf(p, f, 1.0f);
    return p * __int_as_float((ni + 127) << 23);
}

__device__ __forceinline__ void store_split2(__nv_bfloat16* dst2, size_t stride2,
                                             int m, int khalf, int col,
                                             float v0, float v1) {
    __nv_bfloat16 h0 = __float2bfloat16(v0), h1 = __float2bfloat16(v1);
    float l0 = v0 - __bfloat162float(h0), l1 = v1 - __bfloat162float(h1);
    *(__nv_bfloat162*)(dst2 + (size_t)m * stride2 + col) = __halves2bfloat162(h0, h1);
    *(__nv_bfloat162*)(dst2 + (size_t)m * stride2 + khalf + col) = __floats2bfloat162_rn(l0, l1);
}

// ---------------------------------------------------------------------------
// fp32 -> [hi | lo] bf16 split conversion (weights). Rows >= Nrows zeroed.
// ---------------------------------------------------------------------------
__global__ __launch_bounds__(256) void convert_split_kernel(
    const float* __restrict__ X, __nv_bfloat16* __restrict__ X2,
    int Nrows, int K, int Npad)
{
    const long long idx = (long long)blockIdx.x * 256 + threadIdx.x;
    const int kq = K >> 2;
    const long long total = (long long)Npad * kq;
    if (idx >= total) return;
    const int n = (int)(idx / kq);
    const int k = (int)(idx - (long long)n * kq) * 4;
    float4 v = make_float4(0.f, 0.f, 0.f, 0.f);
    if (n < Nrows) v = *(const float4*)(X + (size_t)n * K + k);
    __nv_bfloat16 hx = __float2bfloat16(v.x);
    __nv_bfloat16 hy = __float2bfloat16(v.y);
    __nv_bfloat16 hz = __float2bfloat16(v.z);
    __nv_bfloat16 hw = __float2bfloat16(v.w);
    float lx = v.x - __bfloat162float(hx);
    float ly = v.y - __bfloat162float(hy);
    float lz = v.z - __bfloat162float(hz);
    float lw = v.w - __bfloat162float(hw);
    __nv_bfloat16* row = X2 + (size_t)n * 2 * K;
    __nv_bfloat162* ph = (__nv_bfloat162*)(row + k);
    ph[0] = __halves2bfloat162(hx, hy);
    ph[1] = __halves2bfloat162(hz, hw);
    __nv_bfloat162* pl = (__nv_bfloat162*)(row + K + k);
    pl[0] = __floats2bfloat162_rn(lx, ly);
    pl[1] = __floats2bfloat162_rn(lz, lw);
}

// ---------------------------------------------------------------------------
// Split-bf16 GEMM via mma.sync (unchanged from round 4)
// ---------------------------------------------------------------------------
#define KSTRIDE_B 144
#define ATILE_B  (128 * KSTRIDE_B)
#define BTILE_B  (256 * KSTRIDE_B)
#define GSMEM_TOTAL (2 * ATILE_B + 2 * BTILE_B)

__device__ __forceinline__ void fill_tiles_mma(
    uint32_t aT, uint32_t bT,
    const __nv_bfloat16* __restrict__ A2, const __nv_bfloat16* __restrict__ W2,
    int Kp, int m0, int n0, int ka, int kw, int tid)
{
    #pragma unroll
    for (int i = 0; i < 4; i++) {
        int q = tid + 256 * i;
        int r = q >> 3, c = q & 7;
        cp16(aT + r * KSTRIDE_B + c * 16, A2 + (size_t)(m0 + r) * Kp + ka + c * 8);
    }
    #pragma unroll
    for (int i = 0; i < 8; i++) {
        int q = tid + 256 * i;
        int r = q >> 3, c = q & 7;
        cp16(bT + r * KSTRIDE_B + c * 16, W2 + (size_t)(n0 + r) * Kp + kw + c * 8);
    }
}

template<bool RES>
__global__ __launch_bounds__(256) void mma_gemm(
    const __nv_bfloat16* __restrict__ A2, const __nv_bfloat16* __restrict__ W2,
    const float* __restrict__ bias, const float* __restrict__ res,
    float* __restrict__ C, int K, int Nout)
{
    extern __shared__ char smem[];
    const uint32_t sbase = smem_u32(smem);
    const uint32_t tA[2] = { sbase,                sbase + ATILE_B };
    const uint32_t tB[2] = { sbase + 2 * ATILE_B,  sbase + 2 * ATILE_B + BTILE_B };

    const int tid  = threadIdx.x;
    const int wid  = tid >> 5;
    const int lane = tid & 31;
    const int wm   = wid >> 2;
    const int wn   = wid & 3;
    const int m0 = blockIdx.x * 128;
    const int n0 = blockIdx.y * 256;
    const int Kp = 2 * K;
    const int NCseg = K >> 6;
    const int NC = 3 * NCseg;

    const uint32_t aOff = (uint32_t)((wm * 64 + (lane & 15)) * KSTRIDE_B + (lane >> 4) * 16);
    const uint32_t bOff = (uint32_t)((wn * 64 + (lane & 7) + ((lane >> 4) & 1) * 8) * KSTRIDE_B
                                     + ((lane >> 3) & 1) * 16);

    float acc[4][8][4];
    #pragma unroll
    for (int i = 0; i < 4; i++)
        #pragma unroll
        for (int j = 0; j < 8; j++)
            #pragma unroll
            for (int q = 0; q < 4; q++) acc[i][j][q] = 0.f;

    fill_tiles_mma(tA[0], tB[0], A2, W2, Kp, m0, n0, 0, 0, tid);
    cp_commit();

    for (int c = 0; c < NC; c++) {
        const int b = c & 1;
        if (c + 1 < NC) {
            const int nb = (c + 1) & 1;
            const int cn = c + 1;
            const int seg = cn / NCseg;
            const int kk = (cn - seg * NCseg) << 6;
            const int ka = (seg < 2) ? kk : K + kk;
            const int kw = (seg == 1) ? K + kk : kk;
            fill_tiles_mma(tA[nb], tB[nb], A2, W2, Kp, m0, n0, ka, kw, tid);
            cp_commit();
            cp_wait1();
        } else {
            cp_wait0();
        }
        __syncthreads();

        #pragma unroll
        for (int ks = 0; ks < 4; ks++) {
            const uint32_t kb = (uint32_t)(ks * 32);
            uint32_t a[4][4];
            #pragma unroll
            for (int mf = 0; mf < 4; mf++)
                ldmatrix_x4(a[mf][0], a[mf][1], a[mf][2], a[mf][3],
                            tA[b] + aOff + mf * 16 * KSTRIDE_B + kb);
            uint32_t bb[8][2];
            #pragma unroll
            for (int bf = 0; bf < 4; bf++) {
                uint32_t r0, r1, r2, r3;
                ldmatrix_x4(r0, r1, r2, r3,
                            tB[b] + bOff + bf * 16 * KSTRIDE_B + kb);
                bb[bf * 2 + 0][0] = r0; bb[bf * 2 + 0][1] = r1;
                bb[bf * 2 + 1][0] = r2; bb[bf * 2 + 1][1] = r3;
            }
            #pragma unroll
            for (int mf = 0; mf < 4; mf++)
                #pragma unroll
                for (int nf = 0; nf < 8; nf++)
                    mma_bf16(acc[mf][nf][0], acc[mf][nf][1],
                             acc[mf][nf][2], acc[mf][nf][3],
                             a[mf][0], a[mf][1], a[mf][2], a[mf][3],
                             bb[nf][0], bb[nf][1]);
        }
        __syncthreads();
    }

    const int g = lane >> 2;
    const int t = lane & 3;
    #pragma unroll
    for (int nf = 0; nf < 8; nf++) {
        const int col = n0 + wn * 64 + nf * 8 + t * 2;
        if (col >= Nout) continue;
        const float bx = bias[col], by = bias[col + 1];
        #pragma unroll
        for (int mf = 0; mf < 4; mf++) {
            const int r0 = m0 + wm * 64 + mf * 16 + g;
            float2 v0 = make_float2(acc[mf][nf][0] + bx, acc[mf][nf][1] + by);
            float2 v1 = make_float2(acc[mf][nf][2] + bx, acc[mf][nf][3] + by);
            if (RES) {
                const float2 q0 = *(const float2*)(res + (size_t)r0 * Nout + col);
                const float2 q1 = *(const float2*)(res + (size_t)(r0 + 8) * Nout + col);
                v0.x += q0.x; v0.y += q0.y; v1.x += q1.x; v1.y += q1.y;
            }
            *(float2*)(C + (size_t)r0 * Nout + col) = v0;
            *(float2*)(C + (size_t)(r0 + 8) * Nout + col) = v1;
        }
    }
}

// ---------------------------------------------------------------------------
// RMSNorm -> split-bf16 (fused)
// ---------------------------------------------------------------------------
__global__ __launch_bounds__(256) void rmsnorm_split_kernel(
    const float* __restrict__ x, const float* __restrict__ scale,
    __nv_bfloat16* __restrict__ a2)
{
    const int row = blockIdx.x;
    const float* xr = x + (size_t)row * HID;
    float s = 0.f;
    for (int i = threadIdx.x; i < HID; i += 256) { float v = xr[i]; s += v * v; }
    __shared__ float red[256];
    red[threadIdx.x] = s;
    __syncthreads();
    for (int off = 128; off > 0; off >>= 1) {
        if (threadIdx.x < off) red[threadIdx.x] += red[threadIdx.x + off];
        __syncthreads();
    }
    const float inv = rsqrtf(red[0] / (float)HID + EPSF);
    __nv_bfloat16* rowp = a2 + (size_t)row * 2 * HID;
    for (int i = threadIdx.x * 2; i < HID; i += 512) {
        float v0 = xr[i] * inv * scale[i];
        float v1 = xr[i + 1] * inv * scale[i + 1];
        __nv_bfloat16 h0 = __float2bfloat16(v0), h1 = __float2bfloat16(v1);
        *(__nv_bfloat162*)(rowp + i) = __halves2bfloat162(h0, h1);
        *(__nv_bfloat162*)(rowp + HID + i) = __floats2bfloat162_rn(
            v0 - __bfloat162float(h0), v1 - __bfloat162float(h1));
    }
}

// ---------------------------------------------------------------------------
// RoPE
// ---------------------------------------------------------------------------
__global__ void rope_kernel(float* __restrict__ qkv)
{
    const int t = blockIdx.x;
    const int head = blockIdx.y;
    const int i = threadIdx.x;

    float* base;
    if (head < NH) base = qkv + (size_t)t * QKV_DIM + head * HD;
    else           base = qkv + (size_t)t * QKV_DIM + NH * HD + (head - NH) * HD;

    const float PI = 3.14159265358979323846f;
    const float rope_base = 150000.f;
    const float freq = powf(rope_base, (float)i / 32.f);
    const float conc = 0.1f * logf(32.f) + 1.f;
    const float lg = logf(rope_base);
    const float low  = 32.f * logf(4096.f / (32.f * 2.f * PI)) / lg;
    const float high = 32.f * logf(4096.f / (2.f * PI)) / lg;
    const float interp = 1.f / (32.f * freq);
    const float extrap = 1.f / freq;
    float ramp = ((float)i - low) / (high - low);
    ramp = fminf(fmaxf(ramp, 0.f), 1.f);
    const float mask = 1.f - ramp;
    const float invf = interp * (1.f - mask) + extrap * mask;
    const float ang = (float)t * invf;
    const float c = cosf(ang) * conc;
    const float s = sinf(ang) * conc;

    const float x1 = base[i];
    const float x2 = base[i + 32];
    base[i]      = x1 * c - x2 * s;
    base[i + 32] = x2 * c + x1 * s;
}

// ---------------------------------------------------------------------------
// Causal GQA flash attention via tf32 mma.sync + FMA-pipe exp.
// grid (16, 64), 256 thr (8 warps: 2m x 4n), 64x64 tiles.
// Writes split-bf16 output directly (K=4096 layout for out-GEMM).
// ---------------------------------------------------------------------------
#define ATQ 68
#define ATV 72
#define ATTN_SMEM ((3 * 64 * ATQ + 64 * ATV + 3 * 64 + 2 * 256) * (int)sizeof(float))

__global__ __launch_bounds__(256) void attn_mma_kernel(
    const float* __restrict__ qkv, __nv_bfloat16* __restrict__ o2)
{
    extern __shared__ float sm[];
    float* Qs   = sm;
    float* Ks   = Qs + 64 * ATQ;
    float* Ss   = Ks + 64 * ATQ;
    float* Vs   = Ss + 64 * ATQ;
    float* mrow = Vs + 64 * ATV;
    float* lrow = mrow + 64;
    float* arow = lrow + 64;
    float* pm   = arow + 64;
    float* ps   = pm + 256;

    const int qt = blockIdx.x, h = blockIdx.y, kh = h >> 3;
    const int tid = threadIdx.x, wid = tid >> 5, lane = tid & 31;
    const int wm = wid >> 2, wn = wid & 3;
    const int g = lane >> 2, qd = lane & 3;
    const int sr = tid & 63, sq = tid >> 6;

    for (int i = tid; i < 64 * 64; i += 256) {
        int r = i >> 6, d = i & 63;
        Qs[r * ATQ + d] = tf32r(qkv[(size_t)(qt * 64 + r) * QKV_DIM + h * HD + d]);
    }
    if (tid < 64) { mrow[tid] = -1e30f; lrow[tid] = 0.f; }
    float o[2][2][4];
    #pragma unroll
    for (int i = 0; i < 2; i++)
        #pragma unroll
        for (int j = 0; j < 2; j++)
            #pragma unroll
            for (int q = 0; q < 4; q++) o[i][j][q] = 0.f;
    __syncthreads();

    for (int kt = 0; kt <= qt; kt++) {
        for (int i = tid; i < 64 * 64; i += 256) {
            int r = i >> 6, d = i & 63;
            size_t base = (size_t)(kt * 64 + r) * QKV_DIM;
            Ks[r * ATQ + d] = tf32r(qkv[base + NH * HD + kh * HD + d]);
            Vs[r * ATV + d] = tf32r(qkv[base + (NH + KVH) * HD + kh * HD + d]);
        }
        __syncthreads();

        // S = Q K^T (tf32 mma)
        float s[2][2][4];
        #pragma unroll
        for (int i = 0; i < 2; i++)
            #pragma unroll
            for (int j = 0; j < 2; j++)
                #pragma unroll
                for (int q = 0; q < 4; q++) s[i][j][q] = 0.f;
        #pragma unroll
        for (int k8 = 0; k8 < 8; k8++) {
            const int k0 = k8 * 8;
            uint32_t a[2][4], b[2][2];
            #pragma unroll
            for (int mf = 0; mf < 2; mf++) {
                const int rb = wm * 32 + mf * 16;
                a[mf][0] = __float_as_uint(Qs[(rb + g) * ATQ + k0 + qd]);
                a[mf][1] = __float_as_uint(Qs[(rb + g + 8) * ATQ + k0 + qd]);
                a[mf][2] = __float_as_uint(Qs[(rb + g) * ATQ + k0 + 4 + qd]);
                a[mf][3] = __float_as_uint(Qs[(rb + g + 8) * ATQ + k0 + 4 + qd]);
            }
            #pragma unroll
            for (int nf = 0; nf < 2; nf++) {
                const int nb = wn * 16 + nf * 8;
                b[nf][0] = __float_as_uint(Ks[(nb + g) * ATQ + k0 + qd]);
                b[nf][1] = __float_as_uint(Ks[(nb + g) * ATQ + k0 + 4 + qd]);
            }
            #pragma unroll
            for (int mf = 0; mf < 2; mf++)
                #pragma unroll
                for (int nf = 0; nf < 2; nf++)
                    mma_tf32(s[mf][nf], a[mf], b[nf]);
        }
        #pragma unroll
        for (int mf = 0; mf < 2; mf++)
            #pragma unroll
            for (int nf = 0; nf < 2; nf++) {
                const int r0 = wm * 32 + mf * 16 + g;
                const int c0 = wn * 16 + nf * 8 + 2 * qd;
                *(float2*)&Ss[r0 * ATQ + c0] =
                    make_float2(s[mf][nf][0] * SM_SCALE, s[mf][nf][1] * SM_SCALE);
                *(float2*)&Ss[(r0 + 8) * ATQ + c0] =
                    make_float2(s[mf][nf][2] * SM_SCALE, s[mf][nf][3] * SM_SCALE);
            }
        __syncthreads();

        // parallel online softmax, FMA-pipe exp
        {
            const int cmax = (kt == qt) ? (sr + 1) : 64;
            const int c0 = sq * 16;
            float mx = -1e30f;
            #pragma unroll
            for (int c = c0; c < c0 + 16; c++)
                if (c < cmax) mx = fmaxf(mx, Ss[sr * ATQ + c]);
            pm[sq * 64 + sr] = mx;
            __syncthreads();
            const float mold = mrow[sr];
            const float mfin = fmaxf(mold,
                fmaxf(fmaxf(pm[sr], pm[64 + sr]), fmaxf(pm[128 + sr], pm[192 + sr])));
            float sum = 0.f;
            #pragma unroll
            for (int c = c0; c < c0 + 16; c++) {
                float p = (c < cmax) ? fast_exp(Ss[sr * ATQ + c] - mfin) : 0.f;
                Ss[sr * ATQ + c] = tf32r(p);
                sum += p;
            }
            ps[sq * 64 + sr] = sum;
            __syncthreads();
            if (sq == 0) {
                const float alpha = fast_exp(mold - mfin);
                mrow[sr] = mfin;
                lrow[sr] = lrow[sr] * alpha
                         + ps[sr] + ps[64 + sr] + ps[128 + sr] + ps[192 + sr];
                arow[sr] = alpha;
            }
            __syncthreads();
        }

        // O = O*alpha + P @ V (tf32 mma, accumulate in o frags)
        #pragma unroll
        for (int mf = 0; mf < 2; mf++) {
            const int r0 = wm * 32 + mf * 16 + g;
            const float al0 = arow[r0], al1 = arow[r0 + 8];
            #pragma unroll
            for (int nf = 0; nf < 2; nf++) {
                o[mf][nf][0] *= al0; o[mf][nf][1] *= al0;
                o[mf][nf][2] *= al1; o[mf][nf][3] *= al1;
            }
        }
        #pragma unroll
        for (int k8 = 0; k8 < 8; k8++) {
            const int k0 = k8 * 8;
            uint32_t a[2][4], b[2][2];
            #pragma unroll
            for (int mf = 0; mf < 2; mf++) {
                const int rb = wm * 32 + mf * 16;
                a[mf][0] = __float_as_uint(Ss[(rb + g) * ATQ + k0 + qd]);
                a[mf][1] = __float_as_uint(Ss[(rb + g + 8) * ATQ + k0 + qd]);
                a[mf][2] = __float_as_uint(Ss[(rb + g) * ATQ + k0 + 4 + qd]);
                a[mf][3] = __float_as_uint(Ss[(rb + g + 8) * ATQ + k0 + 4 + qd]);
            }
            #pragma unroll
            for (int nf = 0; nf < 2; nf++) {
                const int nb = wn * 16 + nf * 8;
                b[nf][0] = __float_as_uint(Vs[(k0 + qd) * ATV + nb + g]);
                b[nf][1] = __float_as_uint(Vs[(k0 + 4 + qd) * ATV + nb + g]);
            }
            #pragma unroll
            for (int mf = 0; mf < 2; mf++)
                #pragma unroll
                for (int nf = 0; nf < 2; nf++)
                    mma_tf32(o[mf][nf], a[mf], b[nf]);
        }
        __syncthreads();
    }

    // epilogue: divide by l, write split-bf16 (row stride 2*4096)
    #pragma unroll
    for (int mf = 0; mf < 2; mf++) {
        const int r0 = wm * 32 + mf * 16 + g;
        const float li0 = 1.f / lrow[r0];
        const float li1 = 1.f / lrow[r0 + 8];
        #pragma unroll
        for (int nf = 0; nf < 2; nf++) {
            const int col = h * HD + wn * 16 + nf * 8 + 2 * qd;
            store_split2(o2, 2 * O_DIM, qt * 64 + r0, O_DIM, col,
                         o[mf][nf][0] * li0, o[mf][nf][1] * li0);
            store_split2(o2, 2 * O_DIM, qt * 64 + r0 + 8, O_DIM, col,
                         o[mf][nf][2] * li1, o[mf][nf][3] * li1);
        }
    }
}

// ---------------------------------------------------------------------------
// Clamped SwiGLU -> split-bf16 (fused)
// ---------------------------------------------------------------------------
__global__ __launch_bounds__(256) void act_split_kernel(
    const float* __restrict__ u, __nv_bfloat16* __restrict__ a2)
{
    const int idx = blockIdx.x * 256 + threadIdx.x;
    if (idx >= T_TOK * INTER) return;
    const int row = idx / INTER, col = idx - row * INTER;
    float gx  = u[(size_t)row * U_DIM + 2 * col];
    float lin = u[(size_t)row * U_DIM + 2 * col + 1];
    gx  = fminf(gx, 7.f);
    lin = fminf(fmaxf(lin, -7.f), 7.f);
    const float sg = 1.f / (1.f + fast_exp(-1.702f * gx));
    const float v = gx * sg * (lin + 1.f);
    __nv_bfloat16 hi = __float2bfloat16(v);
    a2[(size_t)row * 2 * INTER + col] = hi;
    a2[(size_t)row * 2 * INTER + INTER + col] =
        __float2bfloat16(v - __bfloat162float(hi));
}

// ---------------------------------------------------------------------------
// Launch
// ---------------------------------------------------------------------------
static inline int cdiv_ll(long long a, int b) { return (int)((a + b - 1) / b); }

extern "C" void kernel_launch(void* const* d_in, const int* in_sizes, int n_in,
                              void* d_out, int out_size)
{
    const float* x        = (const float*)d_in[0];
    const float* an_scale = (const float*)d_in[1];
    const float* wqkv     = (const float*)d_in[2];
    const float* bqkv     = (const float*)d_in[3];
    const float* wout     = (const float*)d_in[4];
    const float* bout     = (const float*)d_in[5];
    const float* mn_scale = (const float*)d_in[6];
    const float* w1       = (const float*)d_in[7];
    const float* b1       = (const float*)d_in[8];
    const float* w2       = (const float*)d_in[9];
    const float* b2       = (const float*)d_in[10];
    float* out = (float*)d_out;

    static float *qkv_p = nullptr, *h_p, *u_p;
    static __nv_bfloat16 *w2qkv_p, *w2out_p, *w2up_p, *w2dn_p, *a2_p;
    if (!qkv_p) {
        cudaGetSymbolAddress((void**)&qkv_p,  g_qkv);
        cudaGetSymbolAddress((void**)&h_p,    g_h);
        cudaGetSymbolAddress((void**)&u_p,    g_u);
        cudaGetSymbolAddress((void**)&w2qkv_p, g_w2_qkv);
        cudaGetSymbolAddress((void**)&w2out_p, g_w2_out);
        cudaGetSymbolAddress((void**)&w2up_p,  g_w2_up);
        cudaGetSymbolAddress((void**)&w2dn_p,  g_w2_dn);
        cudaGetSymbolAddress((void**)&a2_p,    g_a2);
    }
    cudaFuncSetAttribute(attn_mma_kernel,
                         cudaFuncAttributeMaxDynamicSharedMemorySize, ATTN_SMEM);
    cudaFuncSetAttribute(mma_gemm<false>,
                         cudaFuncAttributeMaxDynamicSharedMemorySize, GSMEM_TOTAL);
    cudaFuncSetAttribute(mma_gemm<true>,
                         cudaFuncAttributeMaxDynamicSharedMemorySize, GSMEM_TOTAL);

    // Weight splits
    convert_split_kernel<<<cdiv_ll((long long)QKV_DIM * HID / 4, 256), 256>>>(
        wqkv, w2qkv_p, QKV_DIM, HID, QKV_DIM);
    convert_split_kernel<<<cdiv_ll((long long)NPAD_OUT * O_DIM / 4, 256), 256>>>(
        wout, w2out_p, HID, O_DIM, NPAD_OUT);
    convert_split_kernel<<<cdiv_ll((long long)NPAD_UP * HID / 4, 256), 256>>>(
        w1, w2up_p, U_DIM, HID, NPAD_UP);
    convert_split_kernel<<<cdiv_ll((long long)NPAD_DN * INTER / 4, 256), 256>>>(
        w2, w2dn_p, HID, INTER, NPAD_DN);

    // 1) attn rmsnorm -> split a2
    rmsnorm_split_kernel<<<T_TOK, 256>>>(x, an_scale, a2_p);

    // 2) QKV GEMM
    {
        dim3 grid(T_TOK / 128, QKV_DIM / 256);
        mma_gemm<false><<<grid, 256, GSMEM_TOTAL>>>(a2_p, w2qkv_p, bqkv, nullptr,
                                                    qkv_p, HID, QKV_DIM);
    }

    // 3) RoPE
    {
        dim3 grid(T_TOK, NH + KVH);
        rope_kernel<<<grid, 32>>>(qkv_p);
    }

    // 4) attention (writes split a2, K=4096)
    {
        dim3 grid(T_TOK / 64, NH);
        attn_mma_kernel<<<grid, 256, ATTN_SMEM>>>(qkv_p, a2_p);
    }

    // 5) out GEMM + residual
    {
        dim3 grid(T_TOK / 128, NPAD_OUT / 256);
        mma_gemm<true><<<grid, 256, GSMEM_TOTAL>>>(a2_p, w2out_p, bout, x,
                                                   h_p, O_DIM, HID);
    }

    // 6) mlp rmsnorm -> split a2
    rmsnorm_split_kernel<<<T_TOK, 256>>>(h_p, mn_scale, a2_p);

    // 7) MLP up GEMM
    {
        dim3 grid(T_TOK / 128, NPAD_UP / 256);
        mma_gemm<false><<<grid, 256, GSMEM_TOTAL>>>(a2_p, w2up_p, b1, nullptr,
                                                    u_p, HID, U_DIM);
    }

    // 8) activation -> split a2
    act_split_kernel<<<(T_TOK * INTER + 255) / 256, 256>>>(u_p, a2_p);

    // 9) MLP down GEMM + residual -> out
    {
        dim3 grid(T_TOK / 128, NPAD_DN / 256);
        mma_gemm<true><<<grid, 256, GSMEM_TOTAL>>>(a2_p, w2dn_p, b2, h_p,
                                                   out, INTER, HID);
    }
}